// round 14
// baseline (speedup 1.0000x reference)
#include <cuda_runtime.h>
#include <cuda_fp16.h>
#include <math.h>
#include <math_constants.h>
#include <stdint.h>

#define DIM     1024
#define NHEADS  16
#define HDIM    64
#define HIDDEN  4096
#define BATCH   2
#define SEQ     2048
#define NTOK    (BATCH * SEQ)
#define EPS     1e-5f

// ---------------- scratch (static device globals; no allocs) ----------------
__device__ __half g_h   [NTOK * DIM];         // rmsnorm1 out
__device__ __half g_qkv [NTOK * 3 * DIM];     // fused qkv out (fp16, q pre-scaled)
__device__ __half g_att [NTOK * DIM];         // attention out
__device__ float  g_x2  [NTOK * DIM];         // residual after attention
__device__ __half g_h2  [NTOK * DIM];         // rmsnorm2 out
__device__ __half g_act [NTOK * HIDDEN];      // silu(gate)*up (fp16)
// fp16 weights: wqkv = [wq;wk;wv] rows; wgu rows interleaved gate/up
__device__ __half g_wqkv[3 * DIM * DIM];
__device__ __half g_wo  [DIM * DIM];
__device__ __half g_wgu [2 * HIDDEN * DIM];
__device__ __half g_wd  [DIM * HIDDEN];

// ---------------- helpers ----------------
__device__ __forceinline__ void cp16(unsigned dst, const void* src) {
    asm volatile("cp.async.cg.shared.global [%0], [%1], 16;\n" :: "r"(dst), "l"(src));
}
__device__ __forceinline__ void cp_commit() {
    asm volatile("cp.async.commit_group;\n");
}
template <int N>
__device__ __forceinline__ void cp_wait() {
    asm volatile("cp.async.wait_group %0;\n" :: "n"(N));
}
__device__ __forceinline__ unsigned smem_u32(const void* p) {
    return (unsigned)__cvta_generic_to_shared(p);
}
__device__ __forceinline__ float ex2f(float x) {
    float r; asm("ex2.approx.f32 %0, %1;" : "=f"(r) : "f"(x)); return r;
}
__device__ __forceinline__ float silu_fast(float x) {
    return x / (1.0f + ex2f(-1.44269504089f * x));
}
__device__ __forceinline__ uint32_t packh2(float a, float b) {
    __half2 h = __floats2half2_rn(a, b);
    return *reinterpret_cast<uint32_t*>(&h);
}
__device__ __forceinline__ uint32_t ex2h2(uint32_t x) {
    uint32_t r; asm("ex2.approx.f16x2 %0, %1;" : "=r"(r) : "r"(x)); return r;
}
#define LDMX4(r0, r1, r2, r3, addr) \
    asm volatile("ldmatrix.sync.aligned.m8n8.x4.shared.b16 {%0,%1,%2,%3}, [%4];" \
                 : "=r"(r0), "=r"(r1), "=r"(r2), "=r"(r3) : "r"(addr))
#define LDMX4T(r0, r1, r2, r3, addr) \
    asm volatile("ldmatrix.sync.aligned.m8n8.x4.trans.shared.b16 {%0,%1,%2,%3}, [%4];" \
                 : "=r"(r0), "=r"(r1), "=r"(r2), "=r"(r3) : "r"(addr))
#define MMA16816(c, a0, a1, a2, a3, b0, b1) \
    asm volatile("mma.sync.aligned.m16n8k16.row.col.f32.f16.f16.f32 " \
                 "{%0,%1,%2,%3}, {%4,%5,%6,%7}, {%8,%9}, {%0,%1,%2,%3};" \
                 : "+f"((c)[0]), "+f"((c)[1]), "+f"((c)[2]), "+f"((c)[3]) \
                 : "r"(a0), "r"(a1), "r"(a2), "r"(a3), "r"(b0), "r"(b1))

// softmax scale folded into q at the QKV GEMM epilogue: 1/sqrt(64) * log2(e)
#define ATTN_SC (0.125f * 1.44269504089f)

// ---------------- fp16 tensor-core GEMM core (NT, BK=64, 2-stage) -----------
// 128x128 tile, BK=64, 8 warps (2x4), warp tile 64x32.
// 73.7KB/CTA -> 2 CTAs/SM guaranteed (147KB << 228KB); 16 syncs per K=1024.
#define LDH        72                        // 64 halves + 8 pad (stride 36 words)
#define TILE_BYTES (128 * LDH * 2)           // 18432
#define STG_BYTES  (2 * TILE_BYTES)          // 36864 (A+B per stage)
#define GEMM_DSM   (2 * STG_BYTES)           // 73728

__device__ __forceinline__ void fill_stage_h(unsigned stgbase,
                                             const __half* A, const __half* B,
                                             int K, int m0, int n0, int kt, int tid) {
    int row   = tid >> 1;                    // 0..127
    int cbase = (tid & 1) * 4;               // 16B chunks 0..3 or 4..7
    const __half* ag = A + (size_t)(m0 + row) * K + kt * 64 + cbase * 8;
    const __half* bg = B + (size_t)(n0 + row) * K + kt * 64 + cbase * 8;
    unsigned off = (unsigned)(row * (LDH * 2) + cbase * 16);
    #pragma unroll
    for (int j = 0; j < 4; j++) {
        cp16(stgbase + off + j * 16, ag + j * 8);
        cp16(stgbase + TILE_BYTES + off + j * 16, bg + j * 8);
    }
    cp_commit();
}

__device__ __forceinline__ void gemm_mainloop(float acc[4][4][4],
                                              const __half* A, const __half* B,
                                              int K, int m0, int n0,
                                              int tid, int lane, int wid,
                                              int wm, int wn, unsigned base) {
    #pragma unroll
    for (int i = 0; i < 4; i++)
        #pragma unroll
        for (int j = 0; j < 4; j++)
            #pragma unroll
            for (int c = 0; c < 4; c++) acc[i][j][c] = 0.0f;

    const int NT = K >> 6;                   // BK=64
    fill_stage_h(base, A, B, K, m0, n0, 0, tid);

    unsigned lrow = (unsigned)(lane & 15);
    unsigned lcolb = (unsigned)((lane >> 4) * 16);

    for (int it = 0; it < NT; it++) {
        cp_wait<0>();
        __syncthreads();

        if (it + 1 < NT)
            fill_stage_h(base + ((it + 1) & 1) * STG_BYTES, A, B, K, m0, n0, it + 1, tid);

        unsigned bA = base + (it & 1) * STG_BYTES;
        unsigned bB = bA + TILE_BYTES;
        #pragma unroll
        for (int ks = 0; ks < 4; ks++) {     // 4 x k16 per BK=64
            unsigned kbyte = (unsigned)(ks * 32) + lcolb;
            uint32_t af[4][4], bf[2][4];
            #pragma unroll
            for (int mi = 0; mi < 4; mi++) {
                unsigned addr = bA + (unsigned)((wm + mi * 16 + lrow) * (LDH * 2)) + kbyte;
                LDMX4(af[mi][0], af[mi][1], af[mi][2], af[mi][3], addr);
            }
            #pragma unroll
            for (int nb = 0; nb < 2; nb++) {
                unsigned addr = bB + (unsigned)((wn + nb * 16 + lrow) * (LDH * 2)) + kbyte;
                LDMX4(bf[nb][0], bf[nb][1], bf[nb][2], bf[nb][3], addr);
            }
            #pragma unroll
            for (int mi = 0; mi < 4; mi++) {
                #pragma unroll
                for (int ni = 0; ni < 4; ni++) {
                    int nb = ni >> 1, blk = ni & 1;
                    MMA16816(acc[mi][ni], af[mi][0], af[mi][1], af[mi][2], af[mi][3],
                             bf[nb][blk], bf[nb][blk + 2]);
                }
            }
        }
    }
}

// qsc_cols/qsc: multiply output cols [0, qsc_cols) by qsc (tile-aligned regions).
template<typename OT>
__global__ __launch_bounds__(256, 2)
void gemm_fp16(const __half* __restrict__ A, const __half* __restrict__ B,
               const float* __restrict__ res, OT* __restrict__ C,
               int K, int ldc, int qsc_cols, float qsc) {
    extern __shared__ __half dyn[];
    unsigned base = smem_u32(dyn);
    int tid = threadIdx.x, lane = tid & 31, wid = tid >> 5;
    int wm = (wid & 1) * 64, wn = (wid >> 1) * 32;
    int m0 = blockIdx.y * 128, n0 = blockIdx.x * 128;

    float acc[4][4][4];
    gemm_mainloop(acc, A, B, K, m0, n0, tid, lane, wid, wm, wn, base);

    float sc = (n0 < qsc_cols) ? qsc : 1.0f;
    int gr = lane >> 2;
    int gc = (lane & 3) * 2;
    #pragma unroll
    for (int mi = 0; mi < 4; mi++) {
        #pragma unroll
        for (int ni = 0; ni < 4; ni++) {
            size_t row = (size_t)(m0 + wm + mi * 16 + gr);
            size_t col = (size_t)(n0 + wn + ni * 8 + gc);
            float v[4] = { acc[mi][ni][0] * sc, acc[mi][ni][1] * sc,
                           acc[mi][ni][2] * sc, acc[mi][ni][3] * sc };
            if (res) {
                float2 r0 = *reinterpret_cast<const float2*>(res + row * ldc + col);
                float2 r1 = *reinterpret_cast<const float2*>(res + (row + 8) * ldc + col);
                v[0] += r0.x; v[1] += r0.y; v[2] += r1.x; v[3] += r1.y;
            }
            if (sizeof(OT) == 4) {
                float* Cf = (float*)C;
                *reinterpret_cast<float2*>(Cf + row * ldc + col) = make_float2(v[0], v[1]);
                *reinterpret_cast<float2*>(Cf + (row + 8) * ldc + col) = make_float2(v[2], v[3]);
            } else {
                __half* Ch = (__half*)C;
                *reinterpret_cast<__half2*>(Ch + row * ldc + col) = __floats2half2_rn(v[0], v[1]);
                *reinterpret_cast<__half2*>(Ch + (row + 8) * ldc + col) = __floats2half2_rn(v[2], v[3]);
            }
        }
    }
}

// gate/up GEMM with fused SiLU epilogue. B rows interleaved (2j=gate_j, 2j+1=up_j).
__global__ __launch_bounds__(256, 2)
void gemm_gu(const __half* __restrict__ A, const __half* __restrict__ B,
             __half* __restrict__ act, int K) {
    extern __shared__ __half dyn[];
    unsigned base = smem_u32(dyn);
    int tid = threadIdx.x, lane = tid & 31, wid = tid >> 5;
    int wm = (wid & 1) * 64, wn = (wid >> 1) * 32;
    int m0 = blockIdx.y * 128, n0 = blockIdx.x * 128;

    float acc[4][4][4];
    gemm_mainloop(acc, A, B, K, m0, n0, tid, lane, wid, wm, wn, base);

    int gr = lane >> 2;
    int gc = (lane & 3) * 2;
    #pragma unroll
    for (int mi = 0; mi < 4; mi++) {
        #pragma unroll
        for (int ni = 0; ni < 4; ni++) {
            size_t row = (size_t)(m0 + wm + mi * 16 + gr);
            int col = n0 + wn + ni * 8 + gc;          // even: gate, odd: up
            float r0 = silu_fast(acc[mi][ni][0]) * acc[mi][ni][1];
            float r1 = silu_fast(acc[mi][ni][2]) * acc[mi][ni][3];
            act[row * HIDDEN + (col >> 1)]       = __float2half_rn(r0);
            act[(row + 8) * HIDDEN + (col >> 1)] = __float2half_rn(r1);
        }
    }
}

// ---------------- fp16 tensor-core causal flash attention -------------------
// FROZEN at R13: 64x64 tiles, 4 warps, Q pre-scaled + register-resident,
// fp16x2 exp2, ones-MMA row sums, 2-stage K/V, LPT.
#define LDHA 72
#define LDQKV (3 * DIM)

__global__ __launch_bounds__(128, 4)
void attn_fp16(const __half* __restrict__ QKV, __half* __restrict__ O) {
    __shared__ __half Qs[64 * LDHA];
    __shared__ __half Ks[2][64 * LDHA];
    __shared__ __half Vs[2][64 * LDHA];

    int qb = gridDim.x - 1 - blockIdx.x;   // LPT
    int h = blockIdx.y, b = blockIdx.z;
    int tid = threadIdx.x, lane = tid & 31, wid = tid >> 5;

    const __half* Qg = QKV + (size_t)b * SEQ * LDQKV + h * HDIM;
    const __half* Kg = Qg + DIM;
    const __half* Vg = Qg + 2 * DIM;

    #pragma unroll
    for (int i = 0; i < 4; i++) {
        int id = tid + i * 128;
        int row = id >> 3, ch = id & 7;
        cp16(smem_u32(Qs) + row * (LDHA * 2) + ch * 16,
             Qg + (size_t)(qb * 64 + row) * LDQKV + ch * 8);
    }
    #pragma unroll
    for (int i = 0; i < 4; i++) {
        int id = tid + i * 128;
        int row = id >> 3, ch = id & 7;
        unsigned so = (unsigned)(row * (LDHA * 2) + ch * 16);
        size_t go = (size_t)row * LDQKV + ch * 8;
        cp16(smem_u32(Ks[0]) + so, Kg + go);
        cp16(smem_u32(Vs[0]) + so, Vg + go);
    }
    cp_commit();

    unsigned lrow = (unsigned)(lane & 15);
    unsigned lcolb = (unsigned)((lane >> 4) * 16);

    cp_wait<0>();
    __syncthreads();
    uint32_t qf[4][4];
    {
        unsigned qaddr = smem_u32(Qs) + (wid * 16 + lrow) * (LDHA * 2) + lcolb;
        #pragma unroll
        for (int kk = 0; kk < 4; kk++)
            LDMX4(qf[kk][0], qf[kk][1], qf[kk][2], qf[kk][3], qaddr + kk * 32);
    }

    float o[8][4];
    #pragma unroll
    for (int j = 0; j < 8; j++)
        #pragma unroll
        for (int e = 0; e < 4; e++) o[j][e] = 0.0f;
    float osum[4] = {0.0f, 0.0f, 0.0f, 0.0f};
    float m0 = -CUDART_INF_F, m1 = -CUDART_INF_F;

    uint32_t vb1 = (lane < 4) ? 0x3C003C00u : 0u;

    for (int kb = 0; kb <= qb; kb++) {
        if (kb) __syncthreads();

        if (kb < qb) {
            int s = (kb + 1) & 1;
            #pragma unroll
            for (int i = 0; i < 4; i++) {
                int id = tid + i * 128;
                int row = id >> 3, ch = id & 7;
                unsigned so = (unsigned)(row * (LDHA * 2) + ch * 16);
                size_t go = (size_t)((kb + 1) * 64 + row) * LDQKV + ch * 8;
                cp16(smem_u32(Ks[s]) + so, Kg + go);
                cp16(smem_u32(Vs[s]) + so, Vg + go);
            }
        }
        cp_commit();
        cp_wait<1>();
        __syncthreads();

        int st = kb & 1;
        unsigned kbase = smem_u32(Ks[st]) + lrow * (LDHA * 2) + lcolb;
        unsigned vbase = smem_u32(Vs[st]) + lrow * (LDHA * 2) + lcolb;

        float s[8][4];
        #pragma unroll
        for (int j = 0; j < 8; j++)
            #pragma unroll
            for (int e = 0; e < 4; e++) s[j][e] = 0.0f;
        #pragma unroll
        for (int kk = 0; kk < 4; kk++) {
            #pragma unroll
            for (int nb = 0; nb < 4; nb++) {
                uint32_t b0, b1, b2, b3;
                LDMX4(b0, b1, b2, b3, kbase + (unsigned)(nb * 16 * LDHA * 2) + kk * 32);
                MMA16816(s[nb * 2],     qf[kk][0], qf[kk][1], qf[kk][2], qf[kk][3], b0, b2);
                MMA16816(s[nb * 2 + 1], qf[kk][0], qf[kk][1], qf[kk][2], qf[kk][3], b1, b3);
            }
        }

        int r0 = wid * 16 + (lane >> 2);
        int c0 = (lane & 3) * 2;
        if (kb == qb) {
            #pragma unroll
            for (int j = 0; j < 8; j++) {
                int col = j * 8 + c0;
                #pragma unroll
                for (int e = 0; e < 4; e++) {
                    int row = r0 + (e >> 1) * 8;
                    int cc  = col + (e & 1);
                    if (cc > row) s[j][e] = -CUDART_INF_F;
                }
            }
        }

        float rm0 = -CUDART_INF_F, rm1 = -CUDART_INF_F;
        #pragma unroll
        for (int j = 0; j < 8; j++) {
            rm0 = fmaxf(rm0, fmaxf(s[j][0], s[j][1]));
            rm1 = fmaxf(rm1, fmaxf(s[j][2], s[j][3]));
        }
        rm0 = fmaxf(rm0, __shfl_xor_sync(0xFFFFFFFFu, rm0, 1));
        rm0 = fmaxf(rm0, __shfl_xor_sync(0xFFFFFFFFu, rm0, 2));
        rm1 = fmaxf(rm1, __shfl_xor_sync(0xFFFFFFFFu, rm1, 1));
        rm1 = fmaxf(rm1, __shfl_xor_sync(0xFFFFFFFFu, rm1, 2));
        float mn0 = fmaxf(m0, rm0), mn1 = fmaxf(m1, rm1);
        float a0 = ex2f(m0 - mn0), a1 = ex2f(m1 - mn1);
        m0 = mn0; m1 = mn1;

        #pragma unroll
        for (int j = 0; j < 8; j++) {
            o[j][0] *= a0; o[j][1] *= a0; o[j][2] *= a1; o[j][3] *= a1;
        }
        osum[0] *= a0; osum[1] *= a0; osum[2] *= a1; osum[3] *= a1;

        #pragma unroll
        for (int kk = 0; kk < 4; kk++) {
            uint32_t p0 = ex2h2(packh2(s[2 * kk][0] - mn0,     s[2 * kk][1] - mn0));
            uint32_t p1 = ex2h2(packh2(s[2 * kk][2] - mn1,     s[2 * kk][3] - mn1));
            uint32_t p2 = ex2h2(packh2(s[2 * kk + 1][0] - mn0, s[2 * kk + 1][1] - mn0));
            uint32_t p3 = ex2h2(packh2(s[2 * kk + 1][2] - mn1, s[2 * kk + 1][3] - mn1));
            MMA16816(osum, p0, p1, p2, p3, vb1, vb1);
            #pragma unroll
            for (int nb2 = 0; nb2 < 4; nb2++) {
                uint32_t v0, v1, v2, v3;
                LDMX4T(v0, v1, v2, v3,
                       vbase + (unsigned)(kk * 16 * LDHA * 2) + nb2 * 32);
                MMA16816(o[nb2 * 2],     p0, p1, p2, p3, v0, v1);
                MMA16816(o[nb2 * 2 + 1], p0, p1, p2, p3, v2, v3);
            }
        }
    }

    float l0 = __shfl_sync(0xFFFFFFFFu, osum[0], lane & ~3);
    float l1 = __shfl_sync(0xFFFFFFFFu, osum[2], lane & ~3);

    float inv0 = 1.0f / l0, inv1 = 1.0f / l1;
    int row_g = qb * 64 + wid * 16 + (lane >> 2);
    size_t ob = (size_t)(b * SEQ + row_g) * DIM + h * HDIM + (lane & 3) * 2;
    #pragma unroll
    for (int j = 0; j < 8; j++) {
        *reinterpret_cast<__half2*>(O + ob + j * 8) =
            __floats2half2_rn(o[j][0] * inv0, o[j][1] * inv0);
        *reinterpret_cast<__half2*>(O + ob + 8 * DIM + j * 8) =
            __floats2half2_rn(o[j][2] * inv1, o[j][3] * inv1);
    }
}

// ---------------- single fused weight-conversion kernel ---------------------
__global__ void cvt_all_kernel(const float* __restrict__ wq, const float* __restrict__ wk,
                               const float* __restrict__ wv, const float* __restrict__ wo,
                               const float* __restrict__ wgate, const float* __restrict__ wup,
                               const float* __restrict__ wdown,
                               __half* __restrict__ dqkv, __half* __restrict__ dgu,
                               __half* __restrict__ dwo, __half* __restrict__ dwd) {
    const int nw1 = DIM * DIM / 4, nw2 = HIDDEN * DIM / 4;
    int i = blockIdx.x * blockDim.x + threadIdx.x;
    const float* src;
    __half* dst;
    int di;
    if (i < 3 * nw1) {
        src = (i < nw1) ? (wq + (size_t)i * 4)
            : (i < 2 * nw1) ? (wk + (size_t)(i - nw1) * 4)
            : (wv + (size_t)(i - 2 * nw1) * 4);
        dst = dqkv; di = i;
    } else if (i < 3 * nw1 + 2 * nw2) {
        int j = i - 3 * nw1;
        int r = j >> 8, c = j & 255;
        src = ((r & 1) ? wup : wgate) + (size_t)(r >> 1) * DIM + c * 4;
        dst = dgu; di = j;
    } else if (i < 4 * nw1 + 2 * nw2) {
        int j = i - 3 * nw1 - 2 * nw2;
        src = wo + (size_t)j * 4;
        dst = dwo; di = j;
    } else if (i < 4 * nw1 + 3 * nw2) {
        int j = i - 4 * nw1 - 2 * nw2;
        src = wdown + (size_t)j * 4;
        dst = dwd; di = j;
    } else return;
    float4 v = *reinterpret_cast<const float4*>(src);
    reinterpret_cast<__half2*>(dst)[di * 2]     = __floats2half2_rn(v.x, v.y);
    reinterpret_cast<__half2*>(dst)[di * 2 + 1] = __floats2half2_rn(v.z, v.w);
}

// ---------------- RMSNorm: one block per token, fp16 out ----------------
__global__ void rmsnorm_kernel(const float* __restrict__ x,
                               const float* __restrict__ w,
                               __half* __restrict__ out) {
    int t = blockIdx.x;
    int tid = threadIdx.x;
    const float4* xr = reinterpret_cast<const float4*>(x + (size_t)t * DIM);
    float4 v = xr[tid];
    float ss = v.x * v.x + v.y * v.y + v.z * v.z + v.w * v.w;
    #pragma unroll
    for (int o = 16; o > 0; o >>= 1) ss += __shfl_xor_sync(0xFFFFFFFFu, ss, o);
    __shared__ float red[8];
    if ((tid & 31) == 0) red[tid >> 5] = ss;
    __syncthreads();
    if (tid < 8) {
        float s = red[tid];
        #pragma unroll
        for (int o = 4; o > 0; o >>= 1) s += __shfl_xor_sync(0xFFu, s, o);
        if (tid == 0) red[0] = s;
    }
    __syncthreads();
    float scale = rsqrtf(red[0] * (1.0f / DIM) + EPS);
    float4 wv = reinterpret_cast<const float4*>(w)[tid];
    __half2* op = reinterpret_cast<__half2*>(out + (size_t)t * DIM) + tid * 2;
    op[0] = __floats2half2_rn(v.x * scale * wv.x, v.y * scale * wv.y);
    op[1] = __floats2half2_rn(v.z * scale * wv.z, v.w * scale * wv.w);
}

// ---------------- launch ----------------
extern "C" void kernel_launch(void* const* d_in, const int* in_sizes, int n_in,
                              void* d_out, int out_size) {
    const float* x     = (const float*)d_in[0];
    const float* wq    = (const float*)d_in[1];
    const float* wk    = (const float*)d_in[2];
    const float* wv    = (const float*)d_in[3];
    const float* wo    = (const float*)d_in[4];
    const float* wgate = (const float*)d_in[5];
    const float* wup   = (const float*)d_in[6];
    const float* wdown = (const float*)d_in[7];
    const float* n1w   = (const float*)d_in[8];
    const float* n2w   = (const float*)d_in[9];
    float* out = (float*)d_out;

    __half *h, *qkv, *att, *h2, *act, *cwqkv, *cwo, *cwgu, *cwd;
    float *x2;
    cudaGetSymbolAddress((void**)&h,     g_h);
    cudaGetSymbolAddress((void**)&qkv,   g_qkv);
    cudaGetSymbolAddress((void**)&att,   g_att);
    cudaGetSymbolAddress((void**)&x2,    g_x2);
    cudaGetSymbolAddress((void**)&h2,    g_h2);
    cudaGetSymbolAddress((void**)&act,   g_act);
    cudaGetSymbolAddress((void**)&cwqkv, g_wqkv);
    cudaGetSymbolAddress((void**)&cwo,   g_wo);
    cudaGetSymbolAddress((void**)&cwgu,  g_wgu);
    cudaGetSymbolAddress((void**)&cwd,   g_wd);

    cudaFuncSetAttribute(gemm_fp16<__half>, cudaFuncAttributeMaxDynamicSharedMemorySize, GEMM_DSM);
    cudaFuncSetAttribute(gemm_fp16<float>,  cudaFuncAttributeMaxDynamicSharedMemorySize, GEMM_DSM);
    cudaFuncSetAttribute(gemm_gu,           cudaFuncAttributeMaxDynamicSharedMemorySize, GEMM_DSM);

    // fused weight conversion (all 7 weights, 1 launch)
    int nw1 = DIM * DIM / 4, nw2 = HIDDEN * DIM / 4;
    int ncvt = 4 * nw1 + 3 * nw2;
    cvt_all_kernel<<<(ncvt + 255) / 256, 256>>>(wq, wk, wv, wo, wgate, wup, wdown,
                                                cwqkv, cwgu, cwo, cwd);

    rmsnorm_kernel<<<NTOK, 256>>>(x, n1w, h);

    // fused QKV; q columns [0, DIM) scaled by ATTN_SC in the epilogue
    dim3 gq(3 * DIM / 128, NTOK / 128);
    gemm_fp16<__half><<<gq, 256, GEMM_DSM>>>(h, cwqkv, nullptr, qkv, DIM, 3 * DIM,
                                             DIM, ATTN_SC);

    dim3 ga(SEQ / 64, NHEADS, BATCH);
    attn_fp16<<<ga, 128>>>(qkv, att);

    dim3 g1(DIM / 128, NTOK / 128);
    gemm_fp16<float><<<g1, 256, GEMM_DSM>>>(att, cwo, x, x2, DIM, DIM, 0, 1.0f);

    rmsnorm_kernel<<<NTOK, 256>>>(x2, n2w, h2);

    dim3 g2(2 * HIDDEN / 128, NTOK / 128);
    gemm_gu<<<g2, 256, GEMM_DSM>>>(h2, cwgu, act, DIM);

    gemm_fp16<float><<<g1, 256, GEMM_DSM>>>(act, cwd, x2, out, HIDDEN, DIM, 0, 1.0f);
}

// round 15
// speedup vs baseline: 1.1911x; 1.1911x over previous
#include <cuda_runtime.h>
#include <cuda_fp16.h>
#include <math.h>
#include <math_constants.h>
#include <stdint.h>

#define DIM     1024
#define NHEADS  16
#define HDIM    64
#define HIDDEN  4096
#define BATCH   2
#define SEQ     2048
#define NTOK    (BATCH * SEQ)
#define EPS     1e-5f

// ---------------- scratch (static device globals; no allocs) ----------------
__device__ __half g_h   [NTOK * DIM];         // rmsnorm1 out
__device__ __half g_qkv [NTOK * 3 * DIM];     // fused qkv out (fp16, q pre-scaled)
__device__ __half g_att [NTOK * DIM];         // attention out
__device__ float  g_x2  [NTOK * DIM];         // residual after attention
__device__ __half g_h2  [NTOK * DIM];         // rmsnorm2 out
__device__ __half g_act [NTOK * HIDDEN];      // silu(gate)*up (fp16)
// fp16 weights: wqkv = [wq;wk;wv] rows; wgu rows interleaved gate/up
__device__ __half g_wqkv[3 * DIM * DIM];
__device__ __half g_wo  [DIM * DIM];
__device__ __half g_wgu [2 * HIDDEN * DIM];
__device__ __half g_wd  [DIM * HIDDEN];

// ---------------- helpers ----------------
__device__ __forceinline__ void cp16(unsigned dst, const void* src) {
    asm volatile("cp.async.cg.shared.global [%0], [%1], 16;\n" :: "r"(dst), "l"(src));
}
__device__ __forceinline__ void cp_commit() {
    asm volatile("cp.async.commit_group;\n");
}
template <int N>
__device__ __forceinline__ void cp_wait() {
    asm volatile("cp.async.wait_group %0;\n" :: "n"(N));
}
__device__ __forceinline__ unsigned smem_u32(const void* p) {
    return (unsigned)__cvta_generic_to_shared(p);
}
__device__ __forceinline__ float ex2f(float x) {
    float r; asm("ex2.approx.f32 %0, %1;" : "=f"(r) : "f"(x)); return r;
}
__device__ __forceinline__ float silu_fast(float x) {
    return x / (1.0f + ex2f(-1.44269504089f * x));
}
__device__ __forceinline__ uint32_t packh2(float a, float b) {
    __half2 h = __floats2half2_rn(a, b);
    return *reinterpret_cast<uint32_t*>(&h);
}
__device__ __forceinline__ uint32_t ex2h2(uint32_t x) {
    uint32_t r; asm("ex2.approx.f16x2 %0, %1;" : "=r"(r) : "r"(x)); return r;
}
#define LDMX4(r0, r1, r2, r3, addr) \
    asm volatile("ldmatrix.sync.aligned.m8n8.x4.shared.b16 {%0,%1,%2,%3}, [%4];" \
                 : "=r"(r0), "=r"(r1), "=r"(r2), "=r"(r3) : "r"(addr))
#define LDMX4T(r0, r1, r2, r3, addr) \
    asm volatile("ldmatrix.sync.aligned.m8n8.x4.trans.shared.b16 {%0,%1,%2,%3}, [%4];" \
                 : "=r"(r0), "=r"(r1), "=r"(r2), "=r"(r3) : "r"(addr))
#define MMA16816(c, a0, a1, a2, a3, b0, b1) \
    asm volatile("mma.sync.aligned.m16n8k16.row.col.f32.f16.f16.f32 " \
                 "{%0,%1,%2,%3}, {%4,%5,%6,%7}, {%8,%9}, {%0,%1,%2,%3};" \
                 : "+f"((c)[0]), "+f"((c)[1]), "+f"((c)[2]), "+f"((c)[3]) \
                 : "r"(a0), "r"(a1), "r"(a2), "r"(a3), "r"(b0), "r"(b1))

// softmax scale folded into q at the QKV GEMM epilogue: 1/sqrt(64) * log2(e)
#define ATTN_SC (0.125f * 1.44269504089f)

// ---------------- fp16 tensor-core GEMM core (NT, BK=32, 3-stage) -----------
// CONVERGED configuration: 61.4KB/CTA, 2 CTAs/SM (R9/R10/R14 all regressed off it).
#define LDH        40
#define TILE_BYTES (128 * LDH * 2)          // 10240
#define STG_BYTES  (2 * TILE_BYTES)         // A+B per stage
#define GEMM_DSM   (3 * STG_BYTES)          // 61440 (x2 CTAs = 122880 < 228KB)

struct FillCtx {
    const __half* Ag;     // per-thread global src (row half 0)
    const __half* Bg;
    size_t gstep;         // +64 rows
    unsigned dA, dB;      // per-thread smem dst in stage 0
};

__device__ __forceinline__ FillCtx make_fill(const __half* A, const __half* B,
                                             int K, int m0, int n0,
                                             int tid, unsigned base) {
    FillCtx c;
    int row = tid >> 2;
    int kc  = tid & 3;
    c.Ag = A + (size_t)(m0 + row) * K + kc * 8;
    c.Bg = B + (size_t)(n0 + row) * K + kc * 8;
    c.gstep = (size_t)64 * K;
    unsigned off = (unsigned)(row * LDH * 2 + kc * 16);
    c.dA = base + off;
    c.dB = base + TILE_BYTES + off;
    return c;
}

__device__ __forceinline__ void fill_stage(const FillCtx& c, int st, int kt) {
    unsigned so = (unsigned)(st * STG_BYTES);
    int go = kt * 32;
    cp16(c.dA + so,                 c.Ag + go);
    cp16(c.dA + so + 64 * LDH * 2,  c.Ag + c.gstep + go);
    cp16(c.dB + so,                 c.Bg + go);
    cp16(c.dB + so + 64 * LDH * 2,  c.Bg + c.gstep + go);
    cp_commit();
}

__device__ __forceinline__ void gemm_mainloop(float acc[4][4][4],
                                              const __half* A, const __half* B,
                                              int K, int m0, int n0,
                                              int tid, int lane, int wid,
                                              int wm, int wn, unsigned base) {
    #pragma unroll
    for (int i = 0; i < 4; i++)
        #pragma unroll
        for (int j = 0; j < 4; j++)
            #pragma unroll
            for (int c = 0; c < 4; c++) acc[i][j][c] = 0.0f;

    FillCtx fc = make_fill(A, B, K, m0, n0, tid, base);

    const int NT = K >> 5;
    fill_stage(fc, 0, 0);
    fill_stage(fc, 1, 1);

    unsigned lrow = (unsigned)(lane & 15);
    unsigned lcolb = (unsigned)((lane >> 4) * 16);

    int st = 0;
    for (int it = 0; it < NT; it++) {
        cp_wait<1>();
        __syncthreads();

        if (it + 2 < NT) {
            int fs = st + 2; if (fs >= 3) fs -= 3;
            fill_stage(fc, fs, it + 2);
        }

        unsigned bA = base + st * STG_BYTES;
        unsigned bB = bA + TILE_BYTES;
        #pragma unroll
        for (int ks = 0; ks < 2; ks++) {
            unsigned kbyte = (unsigned)(ks * 32) + lcolb;
            uint32_t af[4][4], bf[2][4];
            #pragma unroll
            for (int mi = 0; mi < 4; mi++) {
                unsigned addr = bA + (unsigned)((wm + mi * 16 + lrow) * LDH * 2) + kbyte;
                LDMX4(af[mi][0], af[mi][1], af[mi][2], af[mi][3], addr);
            }
            #pragma unroll
            for (int nb = 0; nb < 2; nb++) {
                unsigned addr = bB + (unsigned)((wn + nb * 16 + lrow) * LDH * 2) + kbyte;
                LDMX4(bf[nb][0], bf[nb][1], bf[nb][2], bf[nb][3], addr);
            }
            #pragma unroll
            for (int mi = 0; mi < 4; mi++) {
                #pragma unroll
                for (int ni = 0; ni < 4; ni++) {
                    int nb = ni >> 1, blk = ni & 1;
                    MMA16816(acc[mi][ni], af[mi][0], af[mi][1], af[mi][2], af[mi][3],
                             bf[nb][blk], bf[nb][blk + 2]);
                }
            }
        }
        st++; if (st == 3) st = 0;
    }
}

// qsc_cols/qsc: multiply output cols [0, qsc_cols) by qsc (tile-aligned regions).
template<typename OT>
__global__ __launch_bounds__(256, 2)
void gemm_fp16(const __half* __restrict__ A, const __half* __restrict__ B,
               const float* __restrict__ res, OT* __restrict__ C,
               int K, int ldc, int qsc_cols, float qsc) {
    extern __shared__ __half dyn[];
    unsigned base = smem_u32(dyn);
    int tid = threadIdx.x, lane = tid & 31, wid = tid >> 5;
    int wm = (wid & 1) * 64, wn = (wid >> 1) * 32;
    int m0 = blockIdx.y * 128, n0 = blockIdx.x * 128;

    float acc[4][4][4];
    gemm_mainloop(acc, A, B, K, m0, n0, tid, lane, wid, wm, wn, base);

    float sc = (n0 < qsc_cols) ? qsc : 1.0f;
    int gr = lane >> 2;
    int gc = (lane & 3) * 2;
    #pragma unroll
    for (int mi = 0; mi < 4; mi++) {
        #pragma unroll
        for (int ni = 0; ni < 4; ni++) {
            size_t row = (size_t)(m0 + wm + mi * 16 + gr);
            size_t col = (size_t)(n0 + wn + ni * 8 + gc);
            float v[4] = { acc[mi][ni][0] * sc, acc[mi][ni][1] * sc,
                           acc[mi][ni][2] * sc, acc[mi][ni][3] * sc };
            if (res) {
                float2 r0 = *reinterpret_cast<const float2*>(res + row * ldc + col);
                float2 r1 = *reinterpret_cast<const float2*>(res + (row + 8) * ldc + col);
                v[0] += r0.x; v[1] += r0.y; v[2] += r1.x; v[3] += r1.y;
            }
            if (sizeof(OT) == 4) {
                float* Cf = (float*)C;
                *reinterpret_cast<float2*>(Cf + row * ldc + col) = make_float2(v[0], v[1]);
                *reinterpret_cast<float2*>(Cf + (row + 8) * ldc + col) = make_float2(v[2], v[3]);
            } else {
                __half* Ch = (__half*)C;
                *reinterpret_cast<__half2*>(Ch + row * ldc + col) = __floats2half2_rn(v[0], v[1]);
                *reinterpret_cast<__half2*>(Ch + (row + 8) * ldc + col) = __floats2half2_rn(v[2], v[3]);
            }
        }
    }
}

// gate/up GEMM with fused SiLU epilogue. B rows interleaved (2j=gate_j, 2j+1=up_j).
__global__ __launch_bounds__(256, 2)
void gemm_gu(const __half* __restrict__ A, const __half* __restrict__ B,
             __half* __restrict__ act, int K) {
    extern __shared__ __half dyn[];
    unsigned base = smem_u32(dyn);
    int tid = threadIdx.x, lane = tid & 31, wid = tid >> 5;
    int wm = (wid & 1) * 64, wn = (wid >> 1) * 32;
    int m0 = blockIdx.y * 128, n0 = blockIdx.x * 128;

    float acc[4][4][4];
    gemm_mainloop(acc, A, B, K, m0, n0, tid, lane, wid, wm, wn, base);

    int gr = lane >> 2;
    int gc = (lane & 3) * 2;
    #pragma unroll
    for (int mi = 0; mi < 4; mi++) {
        #pragma unroll
        for (int ni = 0; ni < 4; ni++) {
            size_t row = (size_t)(m0 + wm + mi * 16 + gr);
            int col = n0 + wn + ni * 8 + gc;          // even: gate, odd: up
            float r0 = silu_fast(acc[mi][ni][0]) * acc[mi][ni][1];
            float r1 = silu_fast(acc[mi][ni][2]) * acc[mi][ni][3];
            act[row * HIDDEN + (col >> 1)]       = __float2half_rn(r0);
            act[(row + 8) * HIDDEN + (col >> 1)] = __float2half_rn(r1);
        }
    }
}

// ---------------- fp16 tensor-core causal flash attention -------------------
// FROZEN at R13: 64x64 tiles, 4 warps, Q pre-scaled + register-resident,
// fp16x2 exp2, ones-MMA row sums, 2-stage K/V, LPT.
#define LDHA 72
#define LDQKV (3 * DIM)

__global__ __launch_bounds__(128, 4)
void attn_fp16(const __half* __restrict__ QKV, __half* __restrict__ O) {
    __shared__ __half Qs[64 * LDHA];
    __shared__ __half Ks[2][64 * LDHA];
    __shared__ __half Vs[2][64 * LDHA];

    int qb = gridDim.x - 1 - blockIdx.x;   // LPT
    int h = blockIdx.y, b = blockIdx.z;
    int tid = threadIdx.x, lane = tid & 31, wid = tid >> 5;

    const __half* Qg = QKV + (size_t)b * SEQ * LDQKV + h * HDIM;
    const __half* Kg = Qg + DIM;
    const __half* Vg = Qg + 2 * DIM;

    #pragma unroll
    for (int i = 0; i < 4; i++) {
        int id = tid + i * 128;
        int row = id >> 3, ch = id & 7;
        cp16(smem_u32(Qs) + row * (LDHA * 2) + ch * 16,
             Qg + (size_t)(qb * 64 + row) * LDQKV + ch * 8);
    }
    #pragma unroll
    for (int i = 0; i < 4; i++) {
        int id = tid + i * 128;
        int row = id >> 3, ch = id & 7;
        unsigned so = (unsigned)(row * (LDHA * 2) + ch * 16);
        size_t go = (size_t)row * LDQKV + ch * 8;
        cp16(smem_u32(Ks[0]) + so, Kg + go);
        cp16(smem_u32(Vs[0]) + so, Vg + go);
    }
    cp_commit();

    unsigned lrow = (unsigned)(lane & 15);
    unsigned lcolb = (unsigned)((lane >> 4) * 16);

    cp_wait<0>();
    __syncthreads();
    uint32_t qf[4][4];
    {
        unsigned qaddr = smem_u32(Qs) + (wid * 16 + lrow) * (LDHA * 2) + lcolb;
        #pragma unroll
        for (int kk = 0; kk < 4; kk++)
            LDMX4(qf[kk][0], qf[kk][1], qf[kk][2], qf[kk][3], qaddr + kk * 32);
    }

    float o[8][4];
    #pragma unroll
    for (int j = 0; j < 8; j++)
        #pragma unroll
        for (int e = 0; e < 4; e++) o[j][e] = 0.0f;
    float osum[4] = {0.0f, 0.0f, 0.0f, 0.0f};
    float m0 = -CUDART_INF_F, m1 = -CUDART_INF_F;

    uint32_t vb1 = (lane < 4) ? 0x3C003C00u : 0u;

    for (int kb = 0; kb <= qb; kb++) {
        if (kb) __syncthreads();

        if (kb < qb) {
            int s = (kb + 1) & 1;
            #pragma unroll
            for (int i = 0; i < 4; i++) {
                int id = tid + i * 128;
                int row = id >> 3, ch = id & 7;
                unsigned so = (unsigned)(row * (LDHA * 2) + ch * 16);
                size_t go = (size_t)((kb + 1) * 64 + row) * LDQKV + ch * 8;
                cp16(smem_u32(Ks[s]) + so, Kg + go);
                cp16(smem_u32(Vs[s]) + so, Vg + go);
            }
        }
        cp_commit();
        cp_wait<1>();
        __syncthreads();

        int st = kb & 1;
        unsigned kbase = smem_u32(Ks[st]) + lrow * (LDHA * 2) + lcolb;
        unsigned vbase = smem_u32(Vs[st]) + lrow * (LDHA * 2) + lcolb;

        float s[8][4];
        #pragma unroll
        for (int j = 0; j < 8; j++)
            #pragma unroll
            for (int e = 0; e < 4; e++) s[j][e] = 0.0f;
        #pragma unroll
        for (int kk = 0; kk < 4; kk++) {
            #pragma unroll
            for (int nb = 0; nb < 4; nb++) {
                uint32_t b0, b1, b2, b3;
                LDMX4(b0, b1, b2, b3, kbase + (unsigned)(nb * 16 * LDHA * 2) + kk * 32);
                MMA16816(s[nb * 2],     qf[kk][0], qf[kk][1], qf[kk][2], qf[kk][3], b0, b2);
                MMA16816(s[nb * 2 + 1], qf[kk][0], qf[kk][1], qf[kk][2], qf[kk][3], b1, b3);
            }
        }

        int r0 = wid * 16 + (lane >> 2);
        int c0 = (lane & 3) * 2;
        if (kb == qb) {
            #pragma unroll
            for (int j = 0; j < 8; j++) {
                int col = j * 8 + c0;
                #pragma unroll
                for (int e = 0; e < 4; e++) {
                    int row = r0 + (e >> 1) * 8;
                    int cc  = col + (e & 1);
                    if (cc > row) s[j][e] = -CUDART_INF_F;
                }
            }
        }

        float rm0 = -CUDART_INF_F, rm1 = -CUDART_INF_F;
        #pragma unroll
        for (int j = 0; j < 8; j++) {
            rm0 = fmaxf(rm0, fmaxf(s[j][0], s[j][1]));
            rm1 = fmaxf(rm1, fmaxf(s[j][2], s[j][3]));
        }
        rm0 = fmaxf(rm0, __shfl_xor_sync(0xFFFFFFFFu, rm0, 1));
        rm0 = fmaxf(rm0, __shfl_xor_sync(0xFFFFFFFFu, rm0, 2));
        rm1 = fmaxf(rm1, __shfl_xor_sync(0xFFFFFFFFu, rm1, 1));
        rm1 = fmaxf(rm1, __shfl_xor_sync(0xFFFFFFFFu, rm1, 2));
        float mn0 = fmaxf(m0, rm0), mn1 = fmaxf(m1, rm1);
        float a0 = ex2f(m0 - mn0), a1 = ex2f(m1 - mn1);
        m0 = mn0; m1 = mn1;

        #pragma unroll
        for (int j = 0; j < 8; j++) {
            o[j][0] *= a0; o[j][1] *= a0; o[j][2] *= a1; o[j][3] *= a1;
        }
        osum[0] *= a0; osum[1] *= a0; osum[2] *= a1; osum[3] *= a1;

        #pragma unroll
        for (int kk = 0; kk < 4; kk++) {
            uint32_t p0 = ex2h2(packh2(s[2 * kk][0] - mn0,     s[2 * kk][1] - mn0));
            uint32_t p1 = ex2h2(packh2(s[2 * kk][2] - mn1,     s[2 * kk][3] - mn1));
            uint32_t p2 = ex2h2(packh2(s[2 * kk + 1][0] - mn0, s[2 * kk + 1][1] - mn0));
            uint32_t p3 = ex2h2(packh2(s[2 * kk + 1][2] - mn1, s[2 * kk + 1][3] - mn1));
            MMA16816(osum, p0, p1, p2, p3, vb1, vb1);
            #pragma unroll
            for (int nb2 = 0; nb2 < 4; nb2++) {
                uint32_t v0, v1, v2, v3;
                LDMX4T(v0, v1, v2, v3,
                       vbase + (unsigned)(kk * 16 * LDHA * 2) + nb2 * 32);
                MMA16816(o[nb2 * 2],     p0, p1, p2, p3, v0, v1);
                MMA16816(o[nb2 * 2 + 1], p0, p1, p2, p3, v2, v3);
            }
        }
    }

    float l0 = __shfl_sync(0xFFFFFFFFu, osum[0], lane & ~3);
    float l1 = __shfl_sync(0xFFFFFFFFu, osum[2], lane & ~3);

    float inv0 = 1.0f / l0, inv1 = 1.0f / l1;
    int row_g = qb * 64 + wid * 16 + (lane >> 2);
    size_t ob = (size_t)(b * SEQ + row_g) * DIM + h * HDIM + (lane & 3) * 2;
    #pragma unroll
    for (int j = 0; j < 8; j++) {
        *reinterpret_cast<__half2*>(O + ob + j * 8) =
            __floats2half2_rn(o[j][0] * inv0, o[j][1] * inv0);
        *reinterpret_cast<__half2*>(O + ob + 8 * DIM + j * 8) =
            __floats2half2_rn(o[j][2] * inv1, o[j][3] * inv1);
    }
}

// ---------------- single fused weight-conversion kernel ---------------------
__global__ void cvt_all_kernel(const float* __restrict__ wq, const float* __restrict__ wk,
                               const float* __restrict__ wv, const float* __restrict__ wo,
                               const float* __restrict__ wgate, const float* __restrict__ wup,
                               const float* __restrict__ wdown,
                               __half* __restrict__ dqkv, __half* __restrict__ dgu,
                               __half* __restrict__ dwo, __half* __restrict__ dwd) {
    const int nw1 = DIM * DIM / 4, nw2 = HIDDEN * DIM / 4;
    int i = blockIdx.x * blockDim.x + threadIdx.x;
    const float* src;
    __half* dst;
    int di;
    if (i < 3 * nw1) {
        src = (i < nw1) ? (wq + (size_t)i * 4)
            : (i < 2 * nw1) ? (wk + (size_t)(i - nw1) * 4)
            : (wv + (size_t)(i - 2 * nw1) * 4);
        dst = dqkv; di = i;
    } else if (i < 3 * nw1 + 2 * nw2) {
        int j = i - 3 * nw1;
        int r = j >> 8, c = j & 255;
        src = ((r & 1) ? wup : wgate) + (size_t)(r >> 1) * DIM + c * 4;
        dst = dgu; di = j;
    } else if (i < 4 * nw1 + 2 * nw2) {
        int j = i - 3 * nw1 - 2 * nw2;
        src = wo + (size_t)j * 4;
        dst = dwo; di = j;
    } else if (i < 4 * nw1 + 3 * nw2) {
        int j = i - 4 * nw1 - 2 * nw2;
        src = wdown + (size_t)j * 4;
        dst = dwd; di = j;
    } else return;
    float4 v = *reinterpret_cast<const float4*>(src);
    reinterpret_cast<__half2*>(dst)[di * 2]     = __floats2half2_rn(v.x, v.y);
    reinterpret_cast<__half2*>(dst)[di * 2 + 1] = __floats2half2_rn(v.z, v.w);
}

// ---------------- RMSNorm: one block per token, fp16 out ----------------
__global__ void rmsnorm_kernel(const float* __restrict__ x,
                               const float* __restrict__ w,
                               __half* __restrict__ out) {
    int t = blockIdx.x;
    int tid = threadIdx.x;
    const float4* xr = reinterpret_cast<const float4*>(x + (size_t)t * DIM);
    float4 v = xr[tid];
    float ss = v.x * v.x + v.y * v.y + v.z * v.z + v.w * v.w;
    #pragma unroll
    for (int o = 16; o > 0; o >>= 1) ss += __shfl_xor_sync(0xFFFFFFFFu, ss, o);
    __shared__ float red[8];
    if ((tid & 31) == 0) red[tid >> 5] = ss;
    __syncthreads();
    if (tid < 8) {
        float s = red[tid];
        #pragma unroll
        for (int o = 4; o > 0; o >>= 1) s += __shfl_xor_sync(0xFFu, s, o);
        if (tid == 0) red[0] = s;
    }
    __syncthreads();
    float scale = rsqrtf(red[0] * (1.0f / DIM) + EPS);
    float4 wv = reinterpret_cast<const float4*>(w)[tid];
    __half2* op = reinterpret_cast<__half2*>(out + (size_t)t * DIM) + tid * 2;
    op[0] = __floats2half2_rn(v.x * scale * wv.x, v.y * scale * wv.y);
    op[1] = __floats2half2_rn(v.z * scale * wv.z, v.w * scale * wv.w);
}

// ---------------- launch ----------------
extern "C" void kernel_launch(void* const* d_in, const int* in_sizes, int n_in,
                              void* d_out, int out_size) {
    const float* x     = (const float*)d_in[0];
    const float* wq    = (const float*)d_in[1];
    const float* wk    = (const float*)d_in[2];
    const float* wv    = (const float*)d_in[3];
    const float* wo    = (const float*)d_in[4];
    const float* wgate = (const float*)d_in[5];
    const float* wup   = (const float*)d_in[6];
    const float* wdown = (const float*)d_in[7];
    const float* n1w   = (const float*)d_in[8];
    const float* n2w   = (const float*)d_in[9];
    float* out = (float*)d_out;

    __half *h, *qkv, *att, *h2, *act, *cwqkv, *cwo, *cwgu, *cwd;
    float *x2;
    cudaGetSymbolAddress((void**)&h,     g_h);
    cudaGetSymbolAddress((void**)&qkv,   g_qkv);
    cudaGetSymbolAddress((void**)&att,   g_att);
    cudaGetSymbolAddress((void**)&x2,    g_x2);
    cudaGetSymbolAddress((void**)&h2,    g_h2);
    cudaGetSymbolAddress((void**)&act,   g_act);
    cudaGetSymbolAddress((void**)&cwqkv, g_wqkv);
    cudaGetSymbolAddress((void**)&cwo,   g_wo);
    cudaGetSymbolAddress((void**)&cwgu,  g_wgu);
    cudaGetSymbolAddress((void**)&cwd,   g_wd);

    cudaFuncSetAttribute(gemm_fp16<__half>, cudaFuncAttributeMaxDynamicSharedMemorySize, GEMM_DSM);
    cudaFuncSetAttribute(gemm_fp16<float>,  cudaFuncAttributeMaxDynamicSharedMemorySize, GEMM_DSM);
    cudaFuncSetAttribute(gemm_gu,           cudaFuncAttributeMaxDynamicSharedMemorySize, GEMM_DSM);

    // fused weight conversion (all 7 weights, 1 launch)
    int nw1 = DIM * DIM / 4, nw2 = HIDDEN * DIM / 4;
    int ncvt = 4 * nw1 + 3 * nw2;
    cvt_all_kernel<<<(ncvt + 255) / 256, 256>>>(wq, wk, wv, wo, wgate, wup, wdown,
                                                cwqkv, cwgu, cwo, cwd);

    rmsnorm_kernel<<<NTOK, 256>>>(x, n1w, h);

    // fused QKV; q columns [0, DIM) scaled by ATTN_SC in the epilogue
    dim3 gq(3 * DIM / 128, NTOK / 128);
    gemm_fp16<__half><<<gq, 256, GEMM_DSM>>>(h, cwqkv, nullptr, qkv, DIM, 3 * DIM,
                                             DIM, ATTN_SC);

    dim3 ga(SEQ / 64, NHEADS, BATCH);
    attn_fp16<<<ga, 128>>>(qkv, att);

    dim3 g1(DIM / 128, NTOK / 128);
    gemm_fp16<float><<<g1, 256, GEMM_DSM>>>(att, cwo, x, x2, DIM, DIM, 0, 1.0f);

    rmsnorm_kernel<<<NTOK, 256>>>(x2, n2w, h2);

    dim3 g2(2 * HIDDEN / 128, NTOK / 128);
    gemm_gu<<<g2, 256, GEMM_DSM>>>(h2, cwgu, act, DIM);

    gemm_fp16<float><<<g1, 256, GEMM_DSM>>>(act, cwd, x2, out, HIDDEN, DIM, 0, 1.0f);
}

// round 16
// speedup vs baseline: 1.1968x; 1.0048x over previous
#include <cuda_runtime.h>
#include <cuda_fp16.h>
#include <math.h>
#include <math_constants.h>
#include <stdint.h>

#define DIM     1024
#define NHEADS  16
#define HDIM    64
#define HIDDEN  4096
#define BATCH   2
#define SEQ     2048
#define NTOK    (BATCH * SEQ)
#define EPS     1e-5f

// ---------------- scratch (static device globals; no allocs) ----------------
__device__ __half g_h   [NTOK * DIM];         // rmsnorm1 out
__device__ __half g_qkv [NTOK * 3 * DIM];     // fused qkv out (fp16, q pre-scaled)
__device__ __half g_att [NTOK * DIM];         // attention out
__device__ float  g_x2  [NTOK * DIM];         // residual after attention
__device__ __half g_h2  [NTOK * DIM];         // rmsnorm2 out
__device__ __half g_act [NTOK * HIDDEN];      // silu(gate)*up (fp16)
// fp16 weights: wqkv = [wq;wk;wv] rows; wgu rows interleaved gate/up
__device__ __half g_wqkv[3 * DIM * DIM];
__device__ __half g_wo  [DIM * DIM];
__device__ __half g_wgu [2 * HIDDEN * DIM];
__device__ __half g_wd  [DIM * HIDDEN];

// ---------------- helpers ----------------
__device__ __forceinline__ void cp16(unsigned dst, const void* src) {
    asm volatile("cp.async.cg.shared.global [%0], [%1], 16;\n" :: "r"(dst), "l"(src));
}
__device__ __forceinline__ void cp_commit() {
    asm volatile("cp.async.commit_group;\n");
}
template <int N>
__device__ __forceinline__ void cp_wait() {
    asm volatile("cp.async.wait_group %0;\n" :: "n"(N));
}
__device__ __forceinline__ unsigned smem_u32(const void* p) {
    return (unsigned)__cvta_generic_to_shared(p);
}
__device__ __forceinline__ float ex2f(float x) {
    float r; asm("ex2.approx.f32 %0, %1;" : "=f"(r) : "f"(x)); return r;
}
__device__ __forceinline__ float silu_fast(float x) {
    return x / (1.0f + ex2f(-1.44269504089f * x));
}
__device__ __forceinline__ uint32_t packh2(float a, float b) {
    __half2 h = __floats2half2_rn(a, b);
    return *reinterpret_cast<uint32_t*>(&h);
}
__device__ __forceinline__ uint32_t ex2h2(uint32_t x) {
    uint32_t r; asm("ex2.approx.f16x2 %0, %1;" : "=r"(r) : "r"(x)); return r;
}
#define LDMX4(r0, r1, r2, r3, addr) \
    asm volatile("ldmatrix.sync.aligned.m8n8.x4.shared.b16 {%0,%1,%2,%3}, [%4];" \
                 : "=r"(r0), "=r"(r1), "=r"(r2), "=r"(r3) : "r"(addr))
#define LDMX4T(r0, r1, r2, r3, addr) \
    asm volatile("ldmatrix.sync.aligned.m8n8.x4.trans.shared.b16 {%0,%1,%2,%3}, [%4];" \
                 : "=r"(r0), "=r"(r1), "=r"(r2), "=r"(r3) : "r"(addr))
#define MMA16816(c, a0, a1, a2, a3, b0, b1) \
    asm volatile("mma.sync.aligned.m16n8k16.row.col.f32.f16.f16.f32 " \
                 "{%0,%1,%2,%3}, {%4,%5,%6,%7}, {%8,%9}, {%0,%1,%2,%3};" \
                 : "+f"((c)[0]), "+f"((c)[1]), "+f"((c)[2]), "+f"((c)[3]) \
                 : "r"(a0), "r"(a1), "r"(a2), "r"(a3), "r"(b0), "r"(b1))

// softmax scale folded into q at the QKV GEMM epilogue: 1/sqrt(64) * log2(e)
#define ATTN_SC (0.125f * 1.44269504089f)

// ---------------- fp16 tensor-core GEMM core (NT, BK=32, 3-stage) -----------
// CONVERGED configuration (R13): 61.4KB/CTA, 2 CTAs/SM.
#define LDH        40
#define TILE_BYTES (128 * LDH * 2)          // 10240
#define STG_BYTES  (2 * TILE_BYTES)         // A+B per stage
#define GEMM_DSM   (3 * STG_BYTES)          // 61440 (x2 CTAs = 122880 < 228KB)

__device__ __forceinline__ void fill_stage_h(unsigned stgbase,
                                             const __half* A, const __half* B,
                                             int K, int m0, int n0, int kt, int tid) {
    int row = tid >> 2;
    int kc  = tid & 3;
    const __half* ag = A + (size_t)(m0 + row) * K + kt * 32 + kc * 8;
    const __half* bg = B + (size_t)(n0 + row) * K + kt * 32 + kc * 8;
    unsigned off  = (unsigned)(row * LDH * 2 + kc * 16);
    unsigned off2 = off + 64 * LDH * 2;
    size_t gstep = (size_t)64 * K;
    cp16(stgbase + off,  ag);
    cp16(stgbase + off2, ag + gstep);
    cp16(stgbase + TILE_BYTES + off,  bg);
    cp16(stgbase + TILE_BYTES + off2, bg + gstep);
    cp_commit();
}

__device__ __forceinline__ void gemm_mainloop(float acc[4][4][4],
                                              const __half* A, const __half* B,
                                              int K, int m0, int n0,
                                              int tid, int lane, int wid,
                                              int wm, int wn, unsigned base) {
    #pragma unroll
    for (int i = 0; i < 4; i++)
        #pragma unroll
        for (int j = 0; j < 4; j++)
            #pragma unroll
            for (int c = 0; c < 4; c++) acc[i][j][c] = 0.0f;

    const int NT = K >> 5;
    fill_stage_h(base,             A, B, K, m0, n0, 0, tid);
    fill_stage_h(base + STG_BYTES, A, B, K, m0, n0, 1, tid);

    unsigned lrow = (unsigned)(lane & 15);
    unsigned lcolb = (unsigned)((lane >> 4) * 16);

    int st = 0;
    for (int it = 0; it < NT; it++) {
        cp_wait<1>();
        __syncthreads();

        if (it + 2 < NT) {
            int fs = st + 2; if (fs >= 3) fs -= 3;
            fill_stage_h(base + fs * STG_BYTES, A, B, K, m0, n0, it + 2, tid);
        } else {
            cp_commit();
        }

        unsigned bA = base + st * STG_BYTES;
        unsigned bB = bA + TILE_BYTES;
        #pragma unroll
        for (int ks = 0; ks < 2; ks++) {
            unsigned kbyte = (unsigned)(ks * 32) + lcolb;
            uint32_t af[4][4], bf[2][4];
            #pragma unroll
            for (int mi = 0; mi < 4; mi++) {
                unsigned addr = bA + (unsigned)((wm + mi * 16 + lrow) * LDH * 2) + kbyte;
                LDMX4(af[mi][0], af[mi][1], af[mi][2], af[mi][3], addr);
            }
            #pragma unroll
            for (int nb = 0; nb < 2; nb++) {
                unsigned addr = bB + (unsigned)((wn + nb * 16 + lrow) * LDH * 2) + kbyte;
                LDMX4(bf[nb][0], bf[nb][1], bf[nb][2], bf[nb][3], addr);
            }
            #pragma unroll
            for (int mi = 0; mi < 4; mi++) {
                #pragma unroll
                for (int ni = 0; ni < 4; ni++) {
                    int nb = ni >> 1, blk = ni & 1;
                    MMA16816(acc[mi][ni], af[mi][0], af[mi][1], af[mi][2], af[mi][3],
                             bf[nb][blk], bf[nb][blk + 2]);
                }
            }
        }
        st++; if (st == 3) st = 0;
    }
}

// qsc_cols/qsc: multiply output cols [0, qsc_cols) by qsc (tile-aligned regions).
template<typename OT>
__global__ __launch_bounds__(256, 2)
void gemm_fp16(const __half* __restrict__ A, const __half* __restrict__ B,
               const float* __restrict__ res, OT* __restrict__ C,
               int K, int ldc, int qsc_cols, float qsc) {
    extern __shared__ __half dyn[];
    unsigned base = smem_u32(dyn);
    int tid = threadIdx.x, lane = tid & 31, wid = tid >> 5;
    int wm = (wid & 1) * 64, wn = (wid >> 1) * 32;
    int m0 = blockIdx.y * 128, n0 = blockIdx.x * 128;

    float acc[4][4][4];
    gemm_mainloop(acc, A, B, K, m0, n0, tid, lane, wid, wm, wn, base);

    float sc = (n0 < qsc_cols) ? qsc : 1.0f;
    int gr = lane >> 2;
    int gc = (lane & 3) * 2;
    #pragma unroll
    for (int mi = 0; mi < 4; mi++) {
        #pragma unroll
        for (int ni = 0; ni < 4; ni++) {
            size_t row = (size_t)(m0 + wm + mi * 16 + gr);
            size_t col = (size_t)(n0 + wn + ni * 8 + gc);
            float v[4] = { acc[mi][ni][0] * sc, acc[mi][ni][1] * sc,
                           acc[mi][ni][2] * sc, acc[mi][ni][3] * sc };
            if (res) {
                float2 r0 = *reinterpret_cast<const float2*>(res + row * ldc + col);
                float2 r1 = *reinterpret_cast<const float2*>(res + (row + 8) * ldc + col);
                v[0] += r0.x; v[1] += r0.y; v[2] += r1.x; v[3] += r1.y;
            }
            if (sizeof(OT) == 4) {
                float* Cf = (float*)C;
                *reinterpret_cast<float2*>(Cf + row * ldc + col) = make_float2(v[0], v[1]);
                *reinterpret_cast<float2*>(Cf + (row + 8) * ldc + col) = make_float2(v[2], v[3]);
            } else {
                __half* Ch = (__half*)C;
                *reinterpret_cast<__half2*>(Ch + row * ldc + col) = __floats2half2_rn(v[0], v[1]);
                *reinterpret_cast<__half2*>(Ch + (row + 8) * ldc + col) = __floats2half2_rn(v[2], v[3]);
            }
        }
    }
}

// gate/up GEMM with fused SiLU epilogue. B rows interleaved (2j=gate_j, 2j+1=up_j).
__global__ __launch_bounds__(256, 2)
void gemm_gu(const __half* __restrict__ A, const __half* __restrict__ B,
             __half* __restrict__ act, int K) {
    extern __shared__ __half dyn[];
    unsigned base = smem_u32(dyn);
    int tid = threadIdx.x, lane = tid & 31, wid = tid >> 5;
    int wm = (wid & 1) * 64, wn = (wid >> 1) * 32;
    int m0 = blockIdx.y * 128, n0 = blockIdx.x * 128;

    float acc[4][4][4];
    gemm_mainloop(acc, A, B, K, m0, n0, tid, lane, wid, wm, wn, base);

    int gr = lane >> 2;
    int gc = (lane & 3) * 2;
    #pragma unroll
    for (int mi = 0; mi < 4; mi++) {
        #pragma unroll
        for (int ni = 0; ni < 4; ni++) {
            size_t row = (size_t)(m0 + wm + mi * 16 + gr);
            int col = n0 + wn + ni * 8 + gc;          // even: gate, odd: up
            float r0 = silu_fast(acc[mi][ni][0]) * acc[mi][ni][1];
            float r1 = silu_fast(acc[mi][ni][2]) * acc[mi][ni][3];
            act[row * HIDDEN + (col >> 1)]       = __float2half_rn(r0);
            act[(row + 8) * HIDDEN + (col >> 1)] = __float2half_rn(r1);
        }
    }
}

// ---------------- fp16 tensor-core causal flash attention (FROZEN R13) ------
#define LDHA 72
#define LDQKV (3 * DIM)

__global__ __launch_bounds__(128, 4)
void attn_fp16(const __half* __restrict__ QKV, __half* __restrict__ O) {
    __shared__ __half Qs[64 * LDHA];
    __shared__ __half Ks[2][64 * LDHA];
    __shared__ __half Vs[2][64 * LDHA];

    int qb = gridDim.x - 1 - blockIdx.x;   // LPT
    int h = blockIdx.y, b = blockIdx.z;
    int tid = threadIdx.x, lane = tid & 31, wid = tid >> 5;

    const __half* Qg = QKV + (size_t)b * SEQ * LDQKV + h * HDIM;
    const __half* Kg = Qg + DIM;
    const __half* Vg = Qg + 2 * DIM;

    #pragma unroll
    for (int i = 0; i < 4; i++) {
        int id = tid + i * 128;
        int row = id >> 3, ch = id & 7;
        cp16(smem_u32(Qs) + row * (LDHA * 2) + ch * 16,
             Qg + (size_t)(qb * 64 + row) * LDQKV + ch * 8);
    }
    #pragma unroll
    for (int i = 0; i < 4; i++) {
        int id = tid + i * 128;
        int row = id >> 3, ch = id & 7;
        unsigned so = (unsigned)(row * (LDHA * 2) + ch * 16);
        size_t go = (size_t)row * LDQKV + ch * 8;
        cp16(smem_u32(Ks[0]) + so, Kg + go);
        cp16(smem_u32(Vs[0]) + so, Vg + go);
    }
    cp_commit();

    unsigned lrow = (unsigned)(lane & 15);
    unsigned lcolb = (unsigned)((lane >> 4) * 16);

    cp_wait<0>();
    __syncthreads();
    uint32_t qf[4][4];
    {
        unsigned qaddr = smem_u32(Qs) + (wid * 16 + lrow) * (LDHA * 2) + lcolb;
        #pragma unroll
        for (int kk = 0; kk < 4; kk++)
            LDMX4(qf[kk][0], qf[kk][1], qf[kk][2], qf[kk][3], qaddr + kk * 32);
    }

    float o[8][4];
    #pragma unroll
    for (int j = 0; j < 8; j++)
        #pragma unroll
        for (int e = 0; e < 4; e++) o[j][e] = 0.0f;
    float osum[4] = {0.0f, 0.0f, 0.0f, 0.0f};
    float m0 = -CUDART_INF_F, m1 = -CUDART_INF_F;

    uint32_t vb1 = (lane < 4) ? 0x3C003C00u : 0u;

    for (int kb = 0; kb <= qb; kb++) {
        if (kb) __syncthreads();

        if (kb < qb) {
            int s = (kb + 1) & 1;
            #pragma unroll
            for (int i = 0; i < 4; i++) {
                int id = tid + i * 128;
                int row = id >> 3, ch = id & 7;
                unsigned so = (unsigned)(row * (LDHA * 2) + ch * 16);
                size_t go = (size_t)((kb + 1) * 64 + row) * LDQKV + ch * 8;
                cp16(smem_u32(Ks[s]) + so, Kg + go);
                cp16(smem_u32(Vs[s]) + so, Vg + go);
            }
        }
        cp_commit();
        cp_wait<1>();
        __syncthreads();

        int st = kb & 1;
        unsigned kbase = smem_u32(Ks[st]) + lrow * (LDHA * 2) + lcolb;
        unsigned vbase = smem_u32(Vs[st]) + lrow * (LDHA * 2) + lcolb;

        float s[8][4];
        #pragma unroll
        for (int j = 0; j < 8; j++)
            #pragma unroll
            for (int e = 0; e < 4; e++) s[j][e] = 0.0f;
        #pragma unroll
        for (int kk = 0; kk < 4; kk++) {
            #pragma unroll
            for (int nb = 0; nb < 4; nb++) {
                uint32_t b0, b1, b2, b3;
                LDMX4(b0, b1, b2, b3, kbase + (unsigned)(nb * 16 * LDHA * 2) + kk * 32);
                MMA16816(s[nb * 2],     qf[kk][0], qf[kk][1], qf[kk][2], qf[kk][3], b0, b2);
                MMA16816(s[nb * 2 + 1], qf[kk][0], qf[kk][1], qf[kk][2], qf[kk][3], b1, b3);
            }
        }

        int r0 = wid * 16 + (lane >> 2);
        int c0 = (lane & 3) * 2;
        if (kb == qb) {
            #pragma unroll
            for (int j = 0; j < 8; j++) {
                int col = j * 8 + c0;
                #pragma unroll
                for (int e = 0; e < 4; e++) {
                    int row = r0 + (e >> 1) * 8;
                    int cc  = col + (e & 1);
                    if (cc > row) s[j][e] = -CUDART_INF_F;
                }
            }
        }

        float rm0 = -CUDART_INF_F, rm1 = -CUDART_INF_F;
        #pragma unroll
        for (int j = 0; j < 8; j++) {
            rm0 = fmaxf(rm0, fmaxf(s[j][0], s[j][1]));
            rm1 = fmaxf(rm1, fmaxf(s[j][2], s[j][3]));
        }
        rm0 = fmaxf(rm0, __shfl_xor_sync(0xFFFFFFFFu, rm0, 1));
        rm0 = fmaxf(rm0, __shfl_xor_sync(0xFFFFFFFFu, rm0, 2));
        rm1 = fmaxf(rm1, __shfl_xor_sync(0xFFFFFFFFu, rm1, 1));
        rm1 = fmaxf(rm1, __shfl_xor_sync(0xFFFFFFFFu, rm1, 2));
        float mn0 = fmaxf(m0, rm0), mn1 = fmaxf(m1, rm1);
        float a0 = ex2f(m0 - mn0), a1 = ex2f(m1 - mn1);
        m0 = mn0; m1 = mn1;

        #pragma unroll
        for (int j = 0; j < 8; j++) {
            o[j][0] *= a0; o[j][1] *= a0; o[j][2] *= a1; o[j][3] *= a1;
        }
        osum[0] *= a0; osum[1] *= a0; osum[2] *= a1; osum[3] *= a1;

        #pragma unroll
        for (int kk = 0; kk < 4; kk++) {
            uint32_t p0 = ex2h2(packh2(s[2 * kk][0] - mn0,     s[2 * kk][1] - mn0));
            uint32_t p1 = ex2h2(packh2(s[2 * kk][2] - mn1,     s[2 * kk][3] - mn1));
            uint32_t p2 = ex2h2(packh2(s[2 * kk + 1][0] - mn0, s[2 * kk + 1][1] - mn0));
            uint32_t p3 = ex2h2(packh2(s[2 * kk + 1][2] - mn1, s[2 * kk + 1][3] - mn1));
            MMA16816(osum, p0, p1, p2, p3, vb1, vb1);
            #pragma unroll
            for (int nb2 = 0; nb2 < 4; nb2++) {
                uint32_t v0, v1, v2, v3;
                LDMX4T(v0, v1, v2, v3,
                       vbase + (unsigned)(kk * 16 * LDHA * 2) + nb2 * 32);
                MMA16816(o[nb2 * 2],     p0, p1, p2, p3, v0, v1);
                MMA16816(o[nb2 * 2 + 1], p0, p1, p2, p3, v2, v3);
            }
        }
    }

    float l0 = __shfl_sync(0xFFFFFFFFu, osum[0], lane & ~3);
    float l1 = __shfl_sync(0xFFFFFFFFu, osum[2], lane & ~3);

    float inv0 = 1.0f / l0, inv1 = 1.0f / l1;
    int row_g = qb * 64 + wid * 16 + (lane >> 2);
    size_t ob = (size_t)(b * SEQ + row_g) * DIM + h * HDIM + (lane & 3) * 2;
    #pragma unroll
    for (int j = 0; j < 8; j++) {
        *reinterpret_cast<__half2*>(O + ob + j * 8) =
            __floats2half2_rn(o[j][0] * inv0, o[j][1] * inv0);
        *reinterpret_cast<__half2*>(O + ob + 8 * DIM + j * 8) =
            __floats2half2_rn(o[j][2] * inv1, o[j][3] * inv1);
    }
}

// ---------------- fused prologue: rmsnorm1 + all weight conversions ---------
// blocks [0, NTOK): rmsnorm of token blockIdx.x
// blocks [NTOK, NTOK + ncvt/256): weight cvt (256 float4 per block)
__global__ void prologue_kernel(const float* __restrict__ x, const float* __restrict__ n1w,
                                __half* __restrict__ hout,
                                const float* __restrict__ wq, const float* __restrict__ wk,
                                const float* __restrict__ wv, const float* __restrict__ wo,
                                const float* __restrict__ wgate, const float* __restrict__ wup,
                                const float* __restrict__ wdown,
                                __half* __restrict__ dqkv, __half* __restrict__ dgu,
                                __half* __restrict__ dwo, __half* __restrict__ dwd) {
    int tid = threadIdx.x;
    if (blockIdx.x < NTOK) {
        // ---- rmsnorm path ----
        int t = blockIdx.x;
        const float4* xr = reinterpret_cast<const float4*>(x + (size_t)t * DIM);
        float4 v = xr[tid];
        float ss = v.x * v.x + v.y * v.y + v.z * v.z + v.w * v.w;
        #pragma unroll
        for (int o = 16; o > 0; o >>= 1) ss += __shfl_xor_sync(0xFFFFFFFFu, ss, o);
        __shared__ float red[8];
        if ((tid & 31) == 0) red[tid >> 5] = ss;
        __syncthreads();
        if (tid < 8) {
            float s = red[tid];
            #pragma unroll
            for (int o = 4; o > 0; o >>= 1) s += __shfl_xor_sync(0xFFu, s, o);
            if (tid == 0) red[0] = s;
        }
        __syncthreads();
        float scale = rsqrtf(red[0] * (1.0f / DIM) + EPS);
        float4 wv4 = reinterpret_cast<const float4*>(n1w)[tid];
        __half2* op = reinterpret_cast<__half2*>(hout + (size_t)t * DIM) + tid * 2;
        op[0] = __floats2half2_rn(v.x * scale * wv4.x, v.y * scale * wv4.y);
        op[1] = __floats2half2_rn(v.z * scale * wv4.z, v.w * scale * wv4.w);
        return;
    }
    // ---- weight conversion path ----
    const int nw1 = DIM * DIM / 4, nw2 = HIDDEN * DIM / 4;
    int i = (blockIdx.x - NTOK) * blockDim.x + tid;
    const float* src;
    __half* dst;
    int di;
    if (i < 3 * nw1) {
        src = (i < nw1) ? (wq + (size_t)i * 4)
            : (i < 2 * nw1) ? (wk + (size_t)(i - nw1) * 4)
            : (wv + (size_t)(i - 2 * nw1) * 4);
        dst = dqkv; di = i;
    } else if (i < 3 * nw1 + 2 * nw2) {
        int j = i - 3 * nw1;
        int r = j >> 8, c = j & 255;
        src = ((r & 1) ? wup : wgate) + (size_t)(r >> 1) * DIM + c * 4;
        dst = dgu; di = j;
    } else if (i < 4 * nw1 + 2 * nw2) {
        int j = i - 3 * nw1 - 2 * nw2;
        src = wo + (size_t)j * 4;
        dst = dwo; di = j;
    } else if (i < 4 * nw1 + 3 * nw2) {
        int j = i - 4 * nw1 - 2 * nw2;
        src = wdown + (size_t)j * 4;
        dst = dwd; di = j;
    } else return;
    float4 v = *reinterpret_cast<const float4*>(src);
    reinterpret_cast<__half2*>(dst)[di * 2]     = __floats2half2_rn(v.x, v.y);
    reinterpret_cast<__half2*>(dst)[di * 2 + 1] = __floats2half2_rn(v.z, v.w);
}

// ---------------- RMSNorm (standalone, for norm2) ----------------
__global__ void rmsnorm_kernel(const float* __restrict__ x,
                               const float* __restrict__ w,
                               __half* __restrict__ out) {
    int t = blockIdx.x;
    int tid = threadIdx.x;
    const float4* xr = reinterpret_cast<const float4*>(x + (size_t)t * DIM);
    float4 v = xr[tid];
    float ss = v.x * v.x + v.y * v.y + v.z * v.z + v.w * v.w;
    #pragma unroll
    for (int o = 16; o > 0; o >>= 1) ss += __shfl_xor_sync(0xFFFFFFFFu, ss, o);
    __shared__ float red[8];
    if ((tid & 31) == 0) red[tid >> 5] = ss;
    __syncthreads();
    if (tid < 8) {
        float s = red[tid];
        #pragma unroll
        for (int o = 4; o > 0; o >>= 1) s += __shfl_xor_sync(0xFFu, s, o);
        if (tid == 0) red[0] = s;
    }
    __syncthreads();
    float scale = rsqrtf(red[0] * (1.0f / DIM) + EPS);
    float4 wv = reinterpret_cast<const float4*>(w)[tid];
    __half2* op = reinterpret_cast<__half2*>(out + (size_t)t * DIM) + tid * 2;
    op[0] = __floats2half2_rn(v.x * scale * wv.x, v.y * scale * wv.y);
    op[1] = __floats2half2_rn(v.z * scale * wv.z, v.w * scale * wv.w);
}

// ---------------- launch ----------------
extern "C" void kernel_launch(void* const* d_in, const int* in_sizes, int n_in,
                              void* d_out, int out_size) {
    const float* x     = (const float*)d_in[0];
    const float* wq    = (const float*)d_in[1];
    const float* wk    = (const float*)d_in[2];
    const float* wv    = (const float*)d_in[3];
    const float* wo    = (const float*)d_in[4];
    const float* wgate = (const float*)d_in[5];
    const float* wup   = (const float*)d_in[6];
    const float* wdown = (const float*)d_in[7];
    const float* n1w   = (const float*)d_in[8];
    const float* n2w   = (const float*)d_in[9];
    float* out = (float*)d_out;

    __half *h, *qkv, *att, *h2, *act, *cwqkv, *cwo, *cwgu, *cwd;
    float *x2;
    cudaGetSymbolAddress((void**)&h,     g_h);
    cudaGetSymbolAddress((void**)&qkv,   g_qkv);
    cudaGetSymbolAddress((void**)&att,   g_att);
    cudaGetSymbolAddress((void**)&x2,    g_x2);
    cudaGetSymbolAddress((void**)&h2,    g_h2);
    cudaGetSymbolAddress((void**)&act,   g_act);
    cudaGetSymbolAddress((void**)&cwqkv, g_wqkv);
    cudaGetSymbolAddress((void**)&cwo,   g_wo);
    cudaGetSymbolAddress((void**)&cwgu,  g_wgu);
    cudaGetSymbolAddress((void**)&cwd,   g_wd);

    cudaFuncSetAttribute(gemm_fp16<__half>, cudaFuncAttributeMaxDynamicSharedMemorySize, GEMM_DSM);
    cudaFuncSetAttribute(gemm_fp16<float>,  cudaFuncAttributeMaxDynamicSharedMemorySize, GEMM_DSM);
    cudaFuncSetAttribute(gemm_gu,           cudaFuncAttributeMaxDynamicSharedMemorySize, GEMM_DSM);

    // fused prologue: rmsnorm1 (NTOK blocks) + all weight cvt (ncvt/256 blocks)
    int nw1 = DIM * DIM / 4, nw2 = HIDDEN * DIM / 4;
    int ncvt = 4 * nw1 + 3 * nw2;
    int nblk = NTOK + (ncvt + 255) / 256;
    prologue_kernel<<<nblk, 256>>>(x, n1w, h,
                                   wq, wk, wv, wo, wgate, wup, wdown,
                                   cwqkv, cwgu, cwo, cwd);

    // fused QKV; q columns [0, DIM) scaled by ATTN_SC in the epilogue
    dim3 gq(3 * DIM / 128, NTOK / 128);
    gemm_fp16<__half><<<gq, 256, GEMM_DSM>>>(h, cwqkv, nullptr, qkv, DIM, 3 * DIM,
                                             DIM, ATTN_SC);

    dim3 ga(SEQ / 64, NHEADS, BATCH);
    attn_fp16<<<ga, 128>>>(qkv, att);

    dim3 g1(DIM / 128, NTOK / 128);
    gemm_fp16<float><<<g1, 256, GEMM_DSM>>>(att, cwo, x, x2, DIM, DIM, 0, 1.0f);

    rmsnorm_kernel<<<NTOK, 256>>>(x2, n2w, h2);

    dim3 g2(2 * HIDDEN / 128, NTOK / 128);
    gemm_gu<<<g2, 256, GEMM_DSM>>>(h2, cwgu, act, DIM);

    gemm_fp16<float><<<g1, 256, GEMM_DSM>>>(act, cwd, x2, out, HIDDEN, DIM, 0, 1.0f);
}